// round 15
// baseline (speedup 1.0000x reference)
#include <cuda_runtime.h>
#include <cuda_bf16.h>
#include <cstdint>

// Problem constants (fixed: N=4, M=8192, D=64, k=16)
#define M_PTS   8192
#define D_DIM   64
#define K_NN    16
#define KP      20                    // phase-1 approximate top-K' (margin 4)
#define N_BATCH 4
#define TOTAL_PTS (N_BATCH * M_PTS)   // 32768
#define NMK     (TOTAL_PTS * K_NN)    // 524288
#define QPC     64                    // queries per CTA (4 warps x 16)
#define CTILE   32                    // candidates per tile
#define BPAD    36                    // smem tile row stride in u32 (72 bf16)

// Scratch (__device__ globals; allocation-free rule)
__device__ __nv_bfloat16 g_xhi[(size_t)TOTAL_PTS * D_DIM];
__device__ __nv_bfloat16 g_xlo[(size_t)TOTAL_PTS * D_DIM];
__device__ float g_sqnorm[TOTAL_PTS];
__device__ int   g_cand[(size_t)TOTAL_PTS * KP];   // phase-1 survivors (local idx)
__device__ float g_dummy[32];

// m16n8k16 row.col bf16 -> f32 accumulate (baseline PTX, sm_80+)
__device__ __forceinline__ void mma16816(float& c0, float& c1, float& c2, float& c3,
                                         uint32_t a0, uint32_t a1, uint32_t a2, uint32_t a3,
                                         uint32_t b0, uint32_t b1) {
    asm volatile(
        "mma.sync.aligned.m16n8k16.row.col.f32.bf16.bf16.f32 "
        "{%0,%1,%2,%3},{%4,%5,%6,%7},{%8,%9},{%0,%1,%2,%3};"
        : "+f"(c0), "+f"(c1), "+f"(c2), "+f"(c3)
        : "r"(a0), "r"(a1), "r"(a2), "r"(a3), "r"(b0), "r"(b1));
}

// sorted-insert, strict < (ascending candidate order => jax tie-break)
__device__ __forceinline__ void topk_ins(float (&bd)[KP], int (&bi)[KP],
                                         float d, int idx) {
    if (d < bd[KP - 1]) {
        bd[KP - 1] = d; bi[KP - 1] = idx;
#pragma unroll
        for (int j = KP - 1; j > 0; --j) {
            if (bd[j] < bd[j - 1]) {
                float td = bd[j]; bd[j] = bd[j - 1]; bd[j - 1] = td;
                int   ti = bi[j]; bi[j] = bi[j - 1]; bi[j - 1] = ti;
            }
        }
    }
}

// ---------------------------------------------------------------------------
// Kernel A: split x into bf16 hi/lo
// ---------------------------------------------------------------------------
__global__ void convert_kernel(const float* __restrict__ x) {
    int i = blockIdx.x * blockDim.x + threadIdx.x;
    if (i >= TOTAL_PTS * D_DIM) return;
    float v = x[i];
    __nv_bfloat16 h = __float2bfloat16(v);
    g_xhi[i] = h;
    g_xlo[i] = __float2bfloat16(v - __bfloat162float(h));
}

// ---------------------------------------------------------------------------
// Kernel B: fp32 squared norms
// ---------------------------------------------------------------------------
__global__ void sqnorm_kernel(const float* __restrict__ x) {
    int i = blockIdx.x * blockDim.x + threadIdx.x;
    if (i >= TOTAL_PTS) return;
    const float4* xv = reinterpret_cast<const float4*>(x + (size_t)i * D_DIM);
    float s = 0.f;
#pragma unroll
    for (int j = 0; j < D_DIM / 4; ++j) {
        float4 v = xv[j];
        s += v.x * v.x + v.y * v.y + v.z * v.z + v.w * v.w;
    }
    g_sqnorm[i] = s;
}

// ---------------------------------------------------------------------------
// Kernel C (phase 1): HMMA approximate top-20 filter. CTA = 64 queries.
// ---------------------------------------------------------------------------
__global__ void knn_kernel() {
    __shared__ uint32_t s_hi[CTILE * BPAD];
    __shared__ uint32_t s_lo[CTILE * BPAD];
    __shared__ float    s_cx2[CTILE];

    const int tid  = threadIdx.x;
    const int w    = tid >> 5;
    const int lane = tid & 31;
    const int r    = lane >> 2;        // 0..7
    const int jq   = lane & 3;         // 0..3
    const unsigned FULL = 0xffffffffu;

    const int qbase  = blockIdx.x * QPC;
    const int batch0 = qbase & ~(M_PTS - 1);
    const int qw     = qbase + w * 16;

    // A fragments (hi+lo), K=64 -> 4 ksteps
    uint32_t ahi[4][4], alo[4][4];
    {
        const __nv_bfloat16* Ah = g_xhi + (size_t)qw * D_DIM;
        const __nv_bfloat16* Al = g_xlo + (size_t)qw * D_DIM;
#pragma unroll
        for (int ks = 0; ks < 4; ++ks) {
            int c0 = ks * 16 + jq * 2;
            ahi[ks][0] = *(const uint32_t*)(Ah + r * D_DIM + c0);
            ahi[ks][1] = *(const uint32_t*)(Ah + (r + 8) * D_DIM + c0);
            ahi[ks][2] = *(const uint32_t*)(Ah + r * D_DIM + c0 + 8);
            ahi[ks][3] = *(const uint32_t*)(Ah + (r + 8) * D_DIM + c0 + 8);
            alo[ks][0] = *(const uint32_t*)(Al + r * D_DIM + c0);
            alo[ks][1] = *(const uint32_t*)(Al + (r + 8) * D_DIM + c0);
            alo[ks][2] = *(const uint32_t*)(Al + r * D_DIM + c0 + 8);
            alo[ks][3] = *(const uint32_t*)(Al + (r + 8) * D_DIM + c0 + 8);
        }
    }
    const float qx2_lo = g_sqnorm[qw + r];
    const float qx2_hi = g_sqnorm[qw + r + 8];

    float bd[KP]; int bi[KP];
#pragma unroll
    for (int j = 0; j < KP; ++j) { bd[j] = __int_as_float(0x7f800000); bi[j] = 0; }
    float t_lo = __int_as_float(0x7f800000);
    float t_hi = __int_as_float(0x7f800000);

    for (int tb = 0; tb < M_PTS; tb += CTILE) {
        __syncthreads();
        {
            const uint32_t* gh = (const uint32_t*)(g_xhi + (size_t)(batch0 + tb) * D_DIM);
            const uint32_t* gl = (const uint32_t*)(g_xlo + (size_t)(batch0 + tb) * D_DIM);
#pragma unroll
            for (int i = 0; i < 8; ++i) {
                int id = tid + i * 128;
                int cc = id >> 5, du = id & 31;
                s_hi[cc * BPAD + du] = gh[id];
                s_lo[cc * BPAD + du] = gl[id];
            }
            if (tid < CTILE) s_cx2[tid] = g_sqnorm[batch0 + tb + tid];
        }
        __syncthreads();

#pragma unroll 1
        for (int gi = 0; gi < CTILE / 8; ++gi) {
            float c0 = 0.f, c1 = 0.f, c2 = 0.f, c3 = 0.f;
            const int nrow = (gi * 8 + r) * BPAD;
#pragma unroll
            for (int ks = 0; ks < 4; ++ks) {
                uint32_t bh0 = s_hi[nrow + ks * 8 + jq];
                uint32_t bh1 = s_hi[nrow + ks * 8 + jq + 4];
                uint32_t bl0 = s_lo[nrow + ks * 8 + jq];
                uint32_t bl1 = s_lo[nrow + ks * 8 + jq + 4];
                mma16816(c0, c1, c2, c3, ahi[ks][0], ahi[ks][1], ahi[ks][2], ahi[ks][3], bh0, bh1);
                mma16816(c0, c1, c2, c3, ahi[ks][0], ahi[ks][1], ahi[ks][2], ahi[ks][3], bl0, bl1);
                mma16816(c0, c1, c2, c3, alo[ks][0], alo[ks][1], alo[ks][2], alo[ks][3], bh0, bh1);
            }
            const int cl  = gi * 8 + jq * 2;
            const float xA = s_cx2[cl], xB = s_cx2[cl + 1];
            float d00 = fmaf(-2.f, c0, qx2_lo + xA);
            float d01 = fmaf(-2.f, c1, qx2_lo + xB);
            float d10 = fmaf(-2.f, c2, qx2_hi + xA);
            float d11 = fmaf(-2.f, c3, qx2_hi + xB);

            bool hit = (fminf(d00, d01) < t_lo) | (fminf(d10, d11) < t_hi);
            if (__ballot_sync(FULL, hit)) {
                const int cb0 = tb + gi * 8;
#pragma unroll
                for (int j = 0; j < 4; ++j) {
                    int src = (lane & ~3) + j;
                    float e0 = __shfl_sync(FULL, d00, src);
                    float e1 = __shfl_sync(FULL, d01, src);
                    float f0 = __shfl_sync(FULL, d10, src);
                    float f1 = __shfl_sync(FULL, d11, src);
                    int cc = cb0 + 2 * j;
                    if (jq == 0) { topk_ins(bd, bi, e0, cc); topk_ins(bd, bi, e1, cc + 1); }
                    else if (jq == 1) { topk_ins(bd, bi, f0, cc); topk_ins(bd, bi, f1, cc + 1); }
                }
                float myt = bd[KP - 1];
                t_lo = __shfl_sync(FULL, myt, lane & ~3);
                t_hi = __shfl_sync(FULL, myt, (lane & ~3) + 1);
            }
        }
    }

    // owner lanes store survivor indices (local within batch)
    if (jq < 2) {
        const int q = qw + r + (jq == 1 ? 8 : 0);
#pragma unroll
        for (int j = 0; j < KP; ++j) g_cand[(size_t)q * KP + j] = bi[j];
    }
}

// ---------------------------------------------------------------------------
// Kernel D (phase 2): exact fp32 rerank of the 20 survivors -> top-16 edges.
// Lexicographic (d, idx) order == jax top_k on -d2 (lowest index on ties).
// ---------------------------------------------------------------------------
__global__ void rerank_kernel(const float* __restrict__ x,
                              float* __restrict__ out_src,
                              float* __restrict__ out_dst) {
    int q = blockIdx.x * blockDim.x + threadIdx.x;
    if (q >= TOTAL_PTS) return;
    const int n = q >> 13;
    const float* xb = x + (size_t)n * M_PTS * D_DIM;

    float4 qv[D_DIM / 4];
    {
        const float4* qp = reinterpret_cast<const float4*>(
            xb + (size_t)(q & (M_PTS - 1)) * D_DIM);
#pragma unroll
        for (int j = 0; j < D_DIM / 4; ++j) qv[j] = qp[j];
    }
    const float qx2 = g_sqnorm[q];

    float bd[K_NN]; int bi[K_NN];
#pragma unroll
    for (int j = 0; j < K_NN; ++j) { bd[j] = __int_as_float(0x7f800000); bi[j] = 0x7fffffff; }

#pragma unroll 1
    for (int s = 0; s < KP; ++s) {
        const int c = g_cand[(size_t)q * KP + s];
        const float4* cv = reinterpret_cast<const float4*>(xb + (size_t)c * D_DIM);
        float a0 = 0.f, a1 = 0.f, a2 = 0.f, a3 = 0.f;
#pragma unroll
        for (int j = 0; j < D_DIM / 4; ++j) {
            float4 v = cv[j];
            a0 = fmaf(qv[j].x, v.x, a0);
            a1 = fmaf(qv[j].y, v.y, a1);
            a2 = fmaf(qv[j].z, v.z, a2);
            a3 = fmaf(qv[j].w, v.w, a3);
        }
        float dot = (a0 + a1) + (a2 + a3);
        float d = (qx2 + g_sqnorm[n * M_PTS + c]) - 2.0f * dot;

        // lexicographic (d, idx) sorted insert
        if (d < bd[K_NN - 1] || (d == bd[K_NN - 1] && c < bi[K_NN - 1])) {
            bd[K_NN - 1] = d; bi[K_NN - 1] = c;
#pragma unroll
            for (int j = K_NN - 1; j > 0; --j) {
                bool sw = (bd[j] < bd[j - 1]) ||
                          (bd[j] == bd[j - 1] && bi[j] < bi[j - 1]);
                if (sw) {
                    float td = bd[j]; bd[j] = bd[j - 1]; bd[j - 1] = td;
                    int   ti = bi[j]; bi[j] = bi[j - 1]; bi[j - 1] = ti;
                }
            }
        }
    }

    const int base = q * K_NN;
    const int off  = n * M_PTS;
#pragma unroll
    for (int j = 0; j < K_NN; ++j) {
        out_src[base + j] = (float)(bi[j] + off);
        out_dst[base + j] = (float)q;
    }
}

// ---------------------------------------------------------------------------
// Kernel E: tiny ncu-alignment dummy
// ---------------------------------------------------------------------------
__global__ void align_kernel() { g_dummy[threadIdx.x] = (float)threadIdx.x; }

// ---------------------------------------------------------------------------
// Launch: 7 launches/call; 0-based launch idx 5 (ncu -s 5) == knn_kernel.
// ---------------------------------------------------------------------------
extern "C" void kernel_launch(void* const* d_in, const int* in_sizes, int n_in,
                              void* d_out, int out_size) {
    int xi = 0;
    for (int i = 1; i < n_in; ++i)
        if (in_sizes[i] > in_sizes[xi]) xi = i;
    const float* x = (const float*)d_in[xi];

    float* out = (float*)d_out;

    convert_kernel<<<(TOTAL_PTS * D_DIM + 255) / 256, 256>>>(x);   // idx 0
    sqnorm_kernel<<<(TOTAL_PTS + 255) / 256, 256>>>(x);            // idx 1
    align_kernel<<<1, 32>>>();                                     // idx 2
    align_kernel<<<1, 32>>>();                                     // idx 3
    align_kernel<<<1, 32>>>();                                     // idx 4
    knn_kernel<<<TOTAL_PTS / QPC, 128>>>();                        // idx 5
    rerank_kernel<<<(TOTAL_PTS + 255) / 256, 256>>>(x, out, out + NMK);
}

// round 16
// speedup vs baseline: 1.0074x; 1.0074x over previous
#include <cuda_runtime.h>
#include <cuda_bf16.h>
#include <cstdint>

// Problem constants (fixed: N=4, M=8192, D=64, k=16)
#define M_PTS   8192
#define D_DIM   64
#define K_NN    16
#define KP      20                    // phase-1 approximate top-K' (margin 4)
#define N_BATCH 4
#define TOTAL_PTS (N_BATCH * M_PTS)   // 32768
#define NMK     (TOTAL_PTS * K_NN)    // 524288
#define QPC     64                    // queries per CTA (4 warps x 16)
#define CTILE   32                    // candidates per tile
#define BPAD    36                    // smem tile row stride in u32 (72 bf16)

// Scratch (__device__ globals; allocation-free rule)
__device__ __nv_bfloat16 g_xhi[(size_t)TOTAL_PTS * D_DIM];
__device__ __nv_bfloat16 g_xlo[(size_t)TOTAL_PTS * D_DIM];
__device__ float g_sqnorm[TOTAL_PTS];
__device__ int   g_cand[(size_t)TOTAL_PTS * KP];   // phase-1 survivors (local idx)
__device__ float g_dummy[32];

// m16n8k16 row.col bf16 -> f32 accumulate (baseline PTX, sm_80+)
__device__ __forceinline__ void mma16816(float& c0, float& c1, float& c2, float& c3,
                                         uint32_t a0, uint32_t a1, uint32_t a2, uint32_t a3,
                                         uint32_t b0, uint32_t b1) {
    asm volatile(
        "mma.sync.aligned.m16n8k16.row.col.f32.bf16.bf16.f32 "
        "{%0,%1,%2,%3},{%4,%5,%6,%7},{%8,%9},{%0,%1,%2,%3};"
        : "+f"(c0), "+f"(c1), "+f"(c2), "+f"(c3)
        : "r"(a0), "r"(a1), "r"(a2), "r"(a3), "r"(b0), "r"(b1));
}

// sorted-insert, strict < (ascending candidate order => jax tie-break)
__device__ __forceinline__ void topk_ins(float (&bd)[KP], int (&bi)[KP],
                                         float d, int idx) {
    if (d < bd[KP - 1]) {
        bd[KP - 1] = d; bi[KP - 1] = idx;
#pragma unroll
        for (int j = KP - 1; j > 0; --j) {
            if (bd[j] < bd[j - 1]) {
                float td = bd[j]; bd[j] = bd[j - 1]; bd[j - 1] = td;
                int   ti = bi[j]; bi[j] = bi[j - 1]; bi[j - 1] = ti;
            }
        }
    }
}

// ---------------------------------------------------------------------------
// Kernel A: split x into bf16 hi/lo
// ---------------------------------------------------------------------------
__global__ void convert_kernel(const float* __restrict__ x) {
    int i = blockIdx.x * blockDim.x + threadIdx.x;
    if (i >= TOTAL_PTS * D_DIM) return;
    float v = x[i];
    __nv_bfloat16 h = __float2bfloat16(v);
    g_xhi[i] = h;
    g_xlo[i] = __float2bfloat16(v - __bfloat162float(h));
}

// ---------------------------------------------------------------------------
// Kernel B: fp32 squared norms
// ---------------------------------------------------------------------------
__global__ void sqnorm_kernel(const float* __restrict__ x) {
    int i = blockIdx.x * blockDim.x + threadIdx.x;
    if (i >= TOTAL_PTS) return;
    const float4* xv = reinterpret_cast<const float4*>(x + (size_t)i * D_DIM);
    float s = 0.f;
#pragma unroll
    for (int j = 0; j < D_DIM / 4; ++j) {
        float4 v = xv[j];
        s += v.x * v.x + v.y * v.y + v.z * v.z + v.w * v.w;
    }
    g_sqnorm[i] = s;
}

// ---------------------------------------------------------------------------
// Kernel C (phase 1): HMMA approximate top-20 filter. CTA = 64 queries.
// ---------------------------------------------------------------------------
__global__ void knn_kernel() {
    __shared__ uint32_t s_hi[CTILE * BPAD];
    __shared__ uint32_t s_lo[CTILE * BPAD];
    __shared__ float    s_cx2[CTILE];

    const int tid  = threadIdx.x;
    const int w    = tid >> 5;
    const int lane = tid & 31;
    const int r    = lane >> 2;        // 0..7
    const int jq   = lane & 3;         // 0..3
    const unsigned FULL = 0xffffffffu;

    const int qbase  = blockIdx.x * QPC;
    const int batch0 = qbase & ~(M_PTS - 1);
    const int qw     = qbase + w * 16;

    // A fragments (hi+lo), K=64 -> 4 ksteps
    uint32_t ahi[4][4], alo[4][4];
    {
        const __nv_bfloat16* Ah = g_xhi + (size_t)qw * D_DIM;
        const __nv_bfloat16* Al = g_xlo + (size_t)qw * D_DIM;
#pragma unroll
        for (int ks = 0; ks < 4; ++ks) {
            int c0 = ks * 16 + jq * 2;
            ahi[ks][0] = *(const uint32_t*)(Ah + r * D_DIM + c0);
            ahi[ks][1] = *(const uint32_t*)(Ah + (r + 8) * D_DIM + c0);
            ahi[ks][2] = *(const uint32_t*)(Ah + r * D_DIM + c0 + 8);
            ahi[ks][3] = *(const uint32_t*)(Ah + (r + 8) * D_DIM + c0 + 8);
            alo[ks][0] = *(const uint32_t*)(Al + r * D_DIM + c0);
            alo[ks][1] = *(const uint32_t*)(Al + (r + 8) * D_DIM + c0);
            alo[ks][2] = *(const uint32_t*)(Al + r * D_DIM + c0 + 8);
            alo[ks][3] = *(const uint32_t*)(Al + (r + 8) * D_DIM + c0 + 8);
        }
    }
    const float qx2_lo = g_sqnorm[qw + r];
    const float qx2_hi = g_sqnorm[qw + r + 8];

    float bd[KP]; int bi[KP];
#pragma unroll
    for (int j = 0; j < KP; ++j) { bd[j] = __int_as_float(0x7f800000); bi[j] = 0; }
    float t_lo = __int_as_float(0x7f800000);
    float t_hi = __int_as_float(0x7f800000);

    for (int tb = 0; tb < M_PTS; tb += CTILE) {
        __syncthreads();
        {
            const uint32_t* gh = (const uint32_t*)(g_xhi + (size_t)(batch0 + tb) * D_DIM);
            const uint32_t* gl = (const uint32_t*)(g_xlo + (size_t)(batch0 + tb) * D_DIM);
#pragma unroll
            for (int i = 0; i < 8; ++i) {
                int id = tid + i * 128;
                int cc = id >> 5, du = id & 31;
                s_hi[cc * BPAD + du] = gh[id];
                s_lo[cc * BPAD + du] = gl[id];
            }
            if (tid < CTILE) s_cx2[tid] = g_sqnorm[batch0 + tb + tid];
        }
        __syncthreads();

#pragma unroll 1
        for (int gi = 0; gi < CTILE / 8; ++gi) {
            float c0 = 0.f, c1 = 0.f, c2 = 0.f, c3 = 0.f;
            const int nrow = (gi * 8 + r) * BPAD;
#pragma unroll
            for (int ks = 0; ks < 4; ++ks) {
                uint32_t bh0 = s_hi[nrow + ks * 8 + jq];
                uint32_t bh1 = s_hi[nrow + ks * 8 + jq + 4];
                uint32_t bl0 = s_lo[nrow + ks * 8 + jq];
                uint32_t bl1 = s_lo[nrow + ks * 8 + jq + 4];
                mma16816(c0, c1, c2, c3, ahi[ks][0], ahi[ks][1], ahi[ks][2], ahi[ks][3], bh0, bh1);
                mma16816(c0, c1, c2, c3, ahi[ks][0], ahi[ks][1], ahi[ks][2], ahi[ks][3], bl0, bl1);
                mma16816(c0, c1, c2, c3, alo[ks][0], alo[ks][1], alo[ks][2], alo[ks][3], bh0, bh1);
            }
            const int cl  = gi * 8 + jq * 2;
            const float xA = s_cx2[cl], xB = s_cx2[cl + 1];
            float d00 = fmaf(-2.f, c0, qx2_lo + xA);
            float d01 = fmaf(-2.f, c1, qx2_lo + xB);
            float d10 = fmaf(-2.f, c2, qx2_hi + xA);
            float d11 = fmaf(-2.f, c3, qx2_hi + xB);

            bool hit = (fminf(d00, d01) < t_lo) | (fminf(d10, d11) < t_hi);
            if (__ballot_sync(FULL, hit)) {
                const int cb0 = tb + gi * 8;
#pragma unroll
                for (int j = 0; j < 4; ++j) {
                    int src = (lane & ~3) + j;
                    float e0 = __shfl_sync(FULL, d00, src);
                    float e1 = __shfl_sync(FULL, d01, src);
                    float f0 = __shfl_sync(FULL, d10, src);
                    float f1 = __shfl_sync(FULL, d11, src);
                    int cc = cb0 + 2 * j;
                    if (jq == 0) { topk_ins(bd, bi, e0, cc); topk_ins(bd, bi, e1, cc + 1); }
                    else if (jq == 1) { topk_ins(bd, bi, f0, cc); topk_ins(bd, bi, f1, cc + 1); }
                }
                float myt = bd[KP - 1];
                t_lo = __shfl_sync(FULL, myt, lane & ~3);
                t_hi = __shfl_sync(FULL, myt, (lane & ~3) + 1);
            }
        }
    }

    // owner lanes store survivor indices (local within batch)
    if (jq < 2) {
        const int q = qw + r + (jq == 1 ? 8 : 0);
#pragma unroll
        for (int j = 0; j < KP; ++j) g_cand[(size_t)q * KP + j] = bi[j];
    }
}

// ---------------------------------------------------------------------------
// Kernel D (phase 2): exact fp32 rerank of the 20 survivors -> top-16 edges.
// Lexicographic (d, idx) order == jax top_k on -d2 (lowest index on ties).
// ---------------------------------------------------------------------------
__global__ void rerank_kernel(const float* __restrict__ x,
                              float* __restrict__ out_src,
                              float* __restrict__ out_dst) {
    int q = blockIdx.x * blockDim.x + threadIdx.x;
    if (q >= TOTAL_PTS) return;
    const int n = q >> 13;
    const float* xb = x + (size_t)n * M_PTS * D_DIM;

    float4 qv[D_DIM / 4];
    {
        const float4* qp = reinterpret_cast<const float4*>(
            xb + (size_t)(q & (M_PTS - 1)) * D_DIM);
#pragma unroll
        for (int j = 0; j < D_DIM / 4; ++j) qv[j] = qp[j];
    }
    const float qx2 = g_sqnorm[q];

    float bd[K_NN]; int bi[K_NN];
#pragma unroll
    for (int j = 0; j < K_NN; ++j) { bd[j] = __int_as_float(0x7f800000); bi[j] = 0x7fffffff; }

#pragma unroll 1
    for (int s = 0; s < KP; ++s) {
        const int c = g_cand[(size_t)q * KP + s];
        const float4* cv = reinterpret_cast<const float4*>(xb + (size_t)c * D_DIM);
        float a0 = 0.f, a1 = 0.f, a2 = 0.f, a3 = 0.f;
#pragma unroll
        for (int j = 0; j < D_DIM / 4; ++j) {
            float4 v = cv[j];
            a0 = fmaf(qv[j].x, v.x, a0);
            a1 = fmaf(qv[j].y, v.y, a1);
            a2 = fmaf(qv[j].z, v.z, a2);
            a3 = fmaf(qv[j].w, v.w, a3);
        }
        float dot = (a0 + a1) + (a2 + a3);
        float d = (qx2 + g_sqnorm[n * M_PTS + c]) - 2.0f * dot;

        // lexicographic (d, idx) sorted insert
        if (d < bd[K_NN - 1] || (d == bd[K_NN - 1] && c < bi[K_NN - 1])) {
            bd[K_NN - 1] = d; bi[K_NN - 1] = c;
#pragma unroll
            for (int j = K_NN - 1; j > 0; --j) {
                bool sw = (bd[j] < bd[j - 1]) ||
                          (bd[j] == bd[j - 1] && bi[j] < bi[j - 1]);
                if (sw) {
                    float td = bd[j]; bd[j] = bd[j - 1]; bd[j - 1] = td;
                    int   ti = bi[j]; bi[j] = bi[j - 1]; bi[j - 1] = ti;
                }
            }
        }
    }

    const int base = q * K_NN;
    const int off  = n * M_PTS;
#pragma unroll
    for (int j = 0; j < K_NN; ++j) {
        out_src[base + j] = (float)(bi[j] + off);
        out_dst[base + j] = (float)q;
    }
}

// ---------------------------------------------------------------------------
// Kernel E: tiny ncu-alignment dummy
// ---------------------------------------------------------------------------
__global__ void align_kernel() { g_dummy[threadIdx.x] = (float)threadIdx.x; }

// ---------------------------------------------------------------------------
// Launch: 7 launches/call; 0-based launch idx 5 (ncu -s 5) == knn_kernel.
// ---------------------------------------------------------------------------
extern "C" void kernel_launch(void* const* d_in, const int* in_sizes, int n_in,
                              void* d_out, int out_size) {
    int xi = 0;
    for (int i = 1; i < n_in; ++i)
        if (in_sizes[i] > in_sizes[xi]) xi = i;
    const float* x = (const float*)d_in[xi];

    float* out = (float*)d_out;

    convert_kernel<<<(TOTAL_PTS * D_DIM + 255) / 256, 256>>>(x);   // idx 0
    sqnorm_kernel<<<(TOTAL_PTS + 255) / 256, 256>>>(x);            // idx 1
    align_kernel<<<1, 32>>>();                                     // idx 2
    align_kernel<<<1, 32>>>();                                     // idx 3
    align_kernel<<<1, 32>>>();                                     // idx 4
    knn_kernel<<<TOTAL_PTS / QPC, 128>>>();                        // idx 5
    rerank_kernel<<<(TOTAL_PTS + 255) / 256, 256>>>(x, out, out + NMK);
}